// round 1
// baseline (speedup 1.0000x reference)
#include <cuda_runtime.h>
#include <math.h>

// Problem constants
#define BB 4
#define SS 2048
#define EE 1024
#define HH 16
#define DD 64
#define MROWS (BB*SS)          // 8192

// Scratch (device globals -- no allocation allowed)
__device__ float g_Q[BB*HH*SS*DD];      // 32 MB, [bh][s][d]
__device__ float g_K[BB*HH*SS*DD];
__device__ float g_V[BB*HH*SS*DD];
__device__ float g_ctx[MROWS*EE];       // 32 MB, [b*S+s][e]
__device__ float g_cos[SS*32];
__device__ float g_sin[SS*32];

// ---------------------------------------------------------------------------
// RoPE table: cos/sin computed in double for accuracy (angle up to 2047 rad)
// ---------------------------------------------------------------------------
__global__ void rope_table_kernel() {
    int i = blockIdx.x * blockDim.x + threadIdx.x;   // 0 .. S*32-1
    if (i >= SS * 32) return;
    int s = i >> 5;
    int j = i & 31;
    double inv = pow(10000.0, -(double)(2 * j) / 64.0);
    double a = (double)s * inv;
    g_cos[i] = (float)cos(a);
    g_sin[i] = (float)sin(a);
}

// ---------------------------------------------------------------------------
// In-place RoPE on Q and K. One thread per (row, j) pair, j in [0,32).
// ---------------------------------------------------------------------------
__global__ void rope_apply_kernel() {
    int idx = blockIdx.x * blockDim.x + threadIdx.x;
    if (idx >= BB * HH * SS * 32) return;
    int j = idx & 31;
    int r = idx >> 5;                 // (b*H+h)*S + s
    int s = r & (SS - 1);
    float c = g_cos[(s << 5) | j];
    float sn = g_sin[(s << 5) | j];
    size_t base = (size_t)r * DD;

    float q1 = g_Q[base + j], q2 = g_Q[base + j + 32];
    g_Q[base + j]      = q1 * c - q2 * sn;
    g_Q[base + j + 32] = q2 * c + q1 * sn;

    float k1 = g_K[base + j], k2 = g_K[base + j + 32];
    g_K[base + j]      = k1 * c - k2 * sn;
    g_K[base + j + 32] = k2 * c + k1 * sn;
}

// ---------------------------------------------------------------------------
// SGEMM 128x128x16, 256 threads, 8x8 per-thread register tile.
// MODE 0: A = x (arg), C scattered to g_Q/g_K/g_V with bias.
// MODE 1: A = g_ctx, C = d_out (arg) with bias.
// M,N,K are multiples of 128/128/16 here; no bounds checks.
// ---------------------------------------------------------------------------
template <int MODE>
__global__ __launch_bounds__(256)
void sgemm_kernel(const float* __restrict__ Aarg,
                  const float* __restrict__ Bmat,
                  const float* __restrict__ bias,
                  float* __restrict__ Cout,
                  int M, int N, int K) {
    __shared__ float As[16][128];
    __shared__ float Bs[16][128];

    const float* A = (MODE == 1) ? g_ctx : Aarg;

    int tid = threadIdx.x;
    int bm = blockIdx.y * 128;
    int bn = blockIdx.x * 128;

    float acc[8][8];
#pragma unroll
    for (int i = 0; i < 8; i++)
#pragma unroll
        for (int j = 0; j < 8; j++) acc[i][j] = 0.f;

    int arow = tid >> 2;             // 0..63
    int acol = (tid & 3) * 4;        // 0..12
    int brow = tid >> 5;             // 0..7
    int bcol = (tid & 31) * 4;       // 0..124
    int ty = tid >> 4;               // 0..15
    int tx = tid & 15;               // 0..15

    for (int k0 = 0; k0 < K; k0 += 16) {
        // Load A tile (128 x 16), store transposed into As[k][m]
#pragma unroll
        for (int i = 0; i < 2; i++) {
            int r = arow + i * 64;
            float4 v = *(const float4*)(A + (size_t)(bm + r) * K + k0 + acol);
            As[acol + 0][r] = v.x;
            As[acol + 1][r] = v.y;
            As[acol + 2][r] = v.z;
            As[acol + 3][r] = v.w;
        }
        // Load B tile (16 x 128)
#pragma unroll
        for (int i = 0; i < 2; i++) {
            int r = brow + i * 8;
            *(float4*)&Bs[r][bcol] =
                *(const float4*)(Bmat + (size_t)(k0 + r) * N + bn + bcol);
        }
        __syncthreads();

#pragma unroll
        for (int kk = 0; kk < 16; kk++) {
            float af[8], bf[8];
#pragma unroll
            for (int i = 0; i < 8; i++) af[i] = As[kk][ty * 8 + i];
#pragma unroll
            for (int j = 0; j < 8; j++) bf[j] = Bs[kk][tx * 8 + j];
#pragma unroll
            for (int i = 0; i < 8; i++)
#pragma unroll
                for (int j = 0; j < 8; j++) acc[i][j] += af[i] * bf[j];
        }
        __syncthreads();
    }

    // Epilogue
#pragma unroll
    for (int i = 0; i < 8; i++) {
        int row = bm + ty * 8 + i;
#pragma unroll
        for (int j = 0; j < 8; j++) {
            int col = bn + tx * 8 + j;
            float v = acc[i][j] + bias[col];
            if (MODE == 0) {
                int sec = col >> 10;          // 0=q 1=k 2=v
                int w = col & 1023;
                int h = w >> 6;
                int d = w & 63;
                int b = row >> 11;            // /2048
                int s = row & 2047;
                size_t dst = ((size_t)((b * HH + h) * SS + s)) * DD + d;
                float* buf = (sec == 0) ? g_Q : (sec == 1) ? g_K : g_V;
                buf[dst] = v;
            } else {
                Cout[(size_t)row * N + col] = v;
            }
        }
    }
}

// ---------------------------------------------------------------------------
// Flash attention (fp32). Grid: (S/128 q-tiles, B*H). 128 threads/CTA,
// one query row per thread. K/V tiles of 32 keys in smem, scores staged
// in padded smem (bank-conflict-free). Online softmax, causal mask.
// Output written directly in [B,S,E] layout to g_ctx.
// ---------------------------------------------------------------------------
__global__ __launch_bounds__(128)
void flash_kernel() {
    __shared__ float Ks[32][64];
    __shared__ float Vs[32][64];
    __shared__ float Sc[128][33];    // padded: addr = tid*33+k -> bank (tid+k)%32

    int tid = threadIdx.x;
    int bh = blockIdx.y;                     // 0..63
    int q = blockIdx.x * 128 + tid;          // global query pos within (b,h)
    size_t rowbase = ((size_t)bh * SS + q) * DD;

    float Qr[64];
#pragma unroll
    for (int d = 0; d < 64; d += 4) {
        float4 v = *(const float4*)(g_Q + rowbase + d);
        Qr[d] = v.x; Qr[d + 1] = v.y; Qr[d + 2] = v.z; Qr[d + 3] = v.w;
    }

    float O[64];
#pragma unroll
    for (int d = 0; d < 64; d++) O[d] = 0.f;
    float m = -INFINITY, l = 0.f;

    int kend = blockIdx.x * 128 + 128;       // exclusive causal horizon for tile
    size_t kvbase = (size_t)bh * SS * DD;

    for (int k0 = 0; k0 < kend; k0 += 32) {
        // cooperative load of K/V tile: 2048 floats = 512 float4, 4 per thread
#pragma unroll
        for (int i = 0; i < 4; i++) {
            int fi = (tid + i * 128) * 4;
            *(float4*)((float*)Ks + fi) =
                *(const float4*)(g_K + kvbase + (size_t)k0 * DD + fi);
            *(float4*)((float*)Vs + fi) =
                *(const float4*)(g_V + kvbase + (size_t)k0 * DD + fi);
        }
        __syncthreads();

        float tmax = -INFINITY;
#pragma unroll 4
        for (int k = 0; k < 32; k++) {
            float s = 0.f;
#pragma unroll
            for (int d = 0; d < 64; d += 4) {
                float4 kv = *(const float4*)&Ks[k][d];
                s += Qr[d] * kv.x + Qr[d + 1] * kv.y
                   + Qr[d + 2] * kv.z + Qr[d + 3] * kv.w;
            }
            s *= 0.125f;                      // 1/sqrt(64)
            if (k0 + k > q) s = -1e30f;       // causal mask
            Sc[tid][k] = s;
            tmax = fmaxf(tmax, s);
        }

        float mn = fmaxf(m, tmax);
        float corr = __expf(m - mn);          // exp(-inf)=0 on first tile
        l *= corr;
#pragma unroll
        for (int d = 0; d < 64; d++) O[d] *= corr;

#pragma unroll 2
        for (int k = 0; k < 32; k++) {
            float p = __expf(Sc[tid][k] - mn);
            l += p;
#pragma unroll
            for (int d = 0; d < 64; d += 4) {
                float4 vv = *(const float4*)&Vs[k][d];
                O[d]     += p * vv.x;
                O[d + 1] += p * vv.y;
                O[d + 2] += p * vv.z;
                O[d + 3] += p * vv.w;
            }
        }
        m = mn;
        __syncthreads();
    }

    float inv_l = 1.f / l;
    int b = bh >> 4, h = bh & 15;
    size_t obase = ((size_t)(b * SS + q)) * EE + h * DD;
#pragma unroll
    for (int d = 0; d < 64; d += 4) {
        float4 v;
        v.x = O[d] * inv_l;
        v.y = O[d + 1] * inv_l;
        v.z = O[d + 2] * inv_l;
        v.w = O[d + 3] * inv_l;
        *(float4*)(g_ctx + obase + d) = v;
    }
}

// ---------------------------------------------------------------------------
// Launch
// ---------------------------------------------------------------------------
extern "C" void kernel_launch(void* const* d_in, const int* in_sizes, int n_in,
                              void* d_out, int out_size) {
    const float* x      = (const float*)d_in[0];   // [4,2048,1024]
    const float* w_qkv  = (const float*)d_in[1];   // [1024,3072]
    const float* b_qkv  = (const float*)d_in[2];   // [3072]
    const float* w_proj = (const float*)d_in[3];   // [1024,1024]
    const float* b_proj = (const float*)d_in[4];   // [1024]
    float* out = (float*)d_out;                    // [4,2048,1024]

    // 1) RoPE table
    rope_table_kernel<<<(SS * 32 + 255) / 256, 256>>>();

    // 2) QKV GEMM -> scattered Q/K/V head layout
    {
        dim3 grid(3072 / 128, MROWS / 128);        // (24, 64)
        sgemm_kernel<0><<<grid, 256>>>(x, w_qkv, b_qkv, nullptr,
                                       MROWS, 3072, 1024);
    }

    // 3) RoPE in-place on Q,K
    {
        int total = BB * HH * SS * 32;
        rope_apply_kernel<<<(total + 255) / 256, 256>>>();
    }

    // 4) Attention
    {
        dim3 grid(SS / 128, BB * HH);              // (16, 64)
        flash_kernel<<<grid, 128>>>();
    }

    // 5) Output projection -> d_out
    {
        dim3 grid(EE / 128, MROWS / 128);          // (8, 64)
        sgemm_kernel<1><<<grid, 256>>>(nullptr, w_proj, b_proj, out,
                                       MROWS, EE, 1024);
    }
}

// round 3
// speedup vs baseline: 1.6383x; 1.6383x over previous
#include <cuda_runtime.h>
#include <cuda_bf16.h>
#include <math.h>
#include <stdint.h>

// Problem constants
#define BB 4
#define SS 2048
#define EE 1024
#define HH 16
#define DD 64
#define MROWS (BB*SS)          // 8192

// ---------------------------------------------------------------------------
// Scratch (device globals -- no allocation allowed)
// ---------------------------------------------------------------------------
__device__ float g_Q[BB*HH*SS*DD];       // [bh][s][d]
__device__ float g_K[BB*HH*SS*DD];
__device__ float g_V[BB*HH*SS*DD];
__device__ float g_ctx[MROWS*EE];        // [b*S+s][e]
__device__ float g_cos[SS*32];
__device__ float g_sin[SS*32];

__device__ __nv_bfloat16 g_xh[MROWS*EE],   g_xl[MROWS*EE];
__device__ __nv_bfloat16 g_ch[MROWS*EE],   g_cl[MROWS*EE];       // ctx split
__device__ __nv_bfloat16 g_wqh[3072*1024], g_wql[3072*1024];     // w_qkv^T
__device__ __nv_bfloat16 g_wph[1024*1024], g_wpl[1024*1024];     // w_proj^T

// ---------------------------------------------------------------------------
// PTX helpers (baseline PTX only: ldmatrix + mma.sync, legal on compute_103)
// ---------------------------------------------------------------------------
__device__ __forceinline__ uint32_t smem_u32(const void* p) {
    uint32_t a;
    asm("{ .reg .u64 t; cvta.to.shared.u64 t, %1; cvt.u32.u64 %0, t; }"
        : "=r"(a) : "l"(p));
    return a;
}

#define LDSM_X4(r0, r1, r2, r3, addr) \
    asm volatile("ldmatrix.sync.aligned.m8n8.x4.shared.b16 {%0,%1,%2,%3}, [%4];" \
        : "=r"(r0), "=r"(r1), "=r"(r2), "=r"(r3) : "r"(addr))

#define MMA_BF16(c, a, b0, b1) \
    asm volatile("mma.sync.aligned.m16n8k16.row.col.f32.bf16.bf16.f32 " \
        "{%0,%1,%2,%3}, {%4,%5,%6,%7}, {%8,%9}, {%0,%1,%2,%3};" \
        : "+f"((c)[0]), "+f"((c)[1]), "+f"((c)[2]), "+f"((c)[3]) \
        : "r"((a)[0]), "r"((a)[1]), "r"((a)[2]), "r"((a)[3]), \
          "r"(b0), "r"(b1))

// bf16 hi/lo split of two floats, packed as bf16x2 words (x -> low half)
__device__ __forceinline__ void bfsplit2(float x, float y,
                                         uint32_t& hi, uint32_t& lo) {
    __nv_bfloat16 hx = __float2bfloat16(x);
    __nv_bfloat16 hy = __float2bfloat16(y);
    __nv_bfloat16 lx = __float2bfloat16(x - __bfloat162float(hx));
    __nv_bfloat16 ly = __float2bfloat16(y - __bfloat162float(hy));
    __nv_bfloat162 h2 = __halves2bfloat162(hx, hy);
    __nv_bfloat162 l2 = __halves2bfloat162(lx, ly);
    hi = *reinterpret_cast<uint32_t*>(&h2);
    lo = *reinterpret_cast<uint32_t*>(&l2);
}

// ---------------------------------------------------------------------------
// RoPE table (double precision: angle up to ~2047 rad)
// ---------------------------------------------------------------------------
__global__ void rope_table_kernel() {
    int i = blockIdx.x * blockDim.x + threadIdx.x;
    if (i >= SS * 32) return;
    int s = i >> 5;
    int j = i & 31;
    double inv = pow(10000.0, -(double)(2 * j) / 64.0);
    double a = (double)s * inv;
    g_cos[i] = (float)cos(a);
    g_sin[i] = (float)sin(a);
}

// ---------------------------------------------------------------------------
// Split fp32 -> bf16 hi/lo.  which=0: x (arg) -> g_xh/g_xl
//                            which=1: g_ctx   -> g_ch/g_cl
// ---------------------------------------------------------------------------
__global__ void split_kernel(const float* __restrict__ in_arg, int which) {
    int i = blockIdx.x * blockDim.x + threadIdx.x;
    if (i >= MROWS * EE / 4) return;
    const float* in = which ? g_ctx : in_arg;
    __nv_bfloat16* oh = which ? g_ch : g_xh;
    __nv_bfloat16* ol = which ? g_cl : g_xl;
    float4 v = ((const float4*)in)[i];
    uint32_t h0, l0, h1, l1;
    bfsplit2(v.x, v.y, h0, l0);
    bfsplit2(v.z, v.w, h1, l1);
    ((uint2*)oh)[i] = make_uint2(h0, h1);
    ((uint2*)ol)[i] = make_uint2(l0, l1);
}

// ---------------------------------------------------------------------------
// Transpose + split: in [R][C] fp32 -> out [C][R] bf16 hi/lo
// which=0 -> g_wqh/g_wql ; which=1 -> g_wph/g_wpl
// ---------------------------------------------------------------------------
__global__ void transpose_split_kernel(const float* __restrict__ in,
                                       int R, int C, int which) {
    __shared__ float t[32][33];
    __nv_bfloat16* oh = which ? g_wph : g_wqh;
    __nv_bfloat16* ol = which ? g_wpl : g_wql;
    int bx = blockIdx.x * 32, by = blockIdx.y * 32;
#pragma unroll
    for (int i = threadIdx.y; i < 32; i += 8)
        t[i][threadIdx.x] = in[(size_t)(by + i) * C + bx + threadIdx.x];
    __syncthreads();
#pragma unroll
    for (int i = threadIdx.y; i < 32; i += 8) {
        float v = t[threadIdx.x][i];
        __nv_bfloat16 h = __float2bfloat16(v);
        __nv_bfloat16 l = __float2bfloat16(v - __bfloat162float(h));
        size_t idx = (size_t)(bx + i) * R + by + threadIdx.x;
        oh[idx] = h;
        ol[idx] = l;
    }
}

// ---------------------------------------------------------------------------
// HMMA GEMM (bf16 hi/lo split, fp32 acc).  CTA 128x128, K-chunk 64.
// 8 warps in 4(M) x 2(N); warp tile 32x64 = 2 m-tiles x 8 n-tiles of 16x8.
// MODE 0: A=g_xh/xl [8192][1024], B=g_wqh/wql [3072][1024];
//         epilogue = bias + RoPE, scatter to g_Q/g_K/g_V.
// MODE 1: A=g_ch/cl, B=g_wph/wpl [1024][1024]; epilogue = bias -> Cout.
// smem: 4 tiles of [128 rows][64 k] bf16 (16KB each), SW128-XOR swizzle.
// ---------------------------------------------------------------------------
#define OFF_AH 0
#define OFF_AL 16384
#define OFF_BH 32768
#define OFF_BL 49152
#define GEMM_SMEM_BYTES (4*16384 + 1024)

template <int MODE>
__global__ __launch_bounds__(256, 2)
void gemm_mma(const float* __restrict__ bias, float* __restrict__ Cout) {
    extern __shared__ char smem_raw[];
    const uint32_t sb = smem_u32(smem_raw);
    const uint32_t tiles = (sb + 1023u) & ~1023u;
    char* tp = smem_raw + (tiles - sb);

    const __nv_bfloat16* Ah = (MODE == 0) ? g_xh : g_ch;
    const __nv_bfloat16* Al = (MODE == 0) ? g_xl : g_cl;
    const __nv_bfloat16* Bh = (MODE == 0) ? g_wqh : g_wph;
    const __nv_bfloat16* Bl = (MODE == 0) ? g_wql : g_wpl;

    const int tid = threadIdx.x;
    const int lane = tid & 31;
    const int warp = tid >> 5;
    const int wm = warp >> 1;          // 0..3
    const int wn = warp & 1;           // 0..1
    const int bm = blockIdx.y * 128;
    const int bn = blockIdx.x * 128;

    float acc[2][8][4];
#pragma unroll
    for (int mt = 0; mt < 2; mt++)
#pragma unroll
        for (int nt = 0; nt < 8; nt++)
#pragma unroll
            for (int c = 0; c < 4; c++) acc[mt][nt][c] = 0.f;

    // gmem->smem copy mapping: lanes 0..7 = one row's 8 x 16B segments
    const int crow = tid >> 3;         // 0..31
    const int cseg = tid & 7;          // 0..7
    const uint32_t s_off = (uint32_t)(crow * 128 + cseg * 16);
    const uint32_t s_sw = s_off ^ ((s_off >> 3) & 0x70);

    // ldmatrix per-lane row assignment
    const int mat = lane >> 3;         // 0..3
    const int rr = lane & 7;
    // A: mat0=(m0-7,kLo) mat1=(m8-15,kLo) mat2=(m0-7,kHi) mat3=(m8-15,kHi)
    const int a_row_base = wm * 32 + (mat & 1) * 8 + rr;   // + mt*16
    const uint32_t a_k16 = (uint32_t)((mat >> 1) * 16);    // byte offset of k-half
    // B: mat0=(n0-7,kLo) mat1=(n0-7,kHi) mat2=(n8-15,kLo) mat3=(n8-15,kHi)
    const int b_row_base = wn * 64 + (mat >> 1) * 8 + rr;  // + p*16
    const uint32_t b_k16 = (uint32_t)((mat & 1) * 16);

    uint32_t a_addr[2], b_addr[4];
#pragma unroll
    for (int mt = 0; mt < 2; mt++) {
        int row = a_row_base + mt * 16;
        a_addr[mt] = tiles + (uint32_t)(row * 128);
        a_addr[mt] ^= 0;  // keep
        a_addr[mt] += 0;
        a_addr[mt] = tiles + (uint32_t)(row * 128);
        // store xor-key in high-level var below
    }
    uint32_t a_xor[2], b_xor[4];
#pragma unroll
    for (int mt = 0; mt < 2; mt++) {
        int row = a_row_base + mt * 16;
        a_addr[mt] = tiles + (uint32_t)(row * 128);
        a_xor[mt] = (uint32_t)((row & 7) << 4);
    }
#pragma unroll
    for (int p = 0; p < 4; p++) {
        int row = b_row_base + p * 16;
        b_addr[p] = tiles + (uint32_t)(row * 128);
        b_xor[p] = (uint32_t)((row & 7) << 4);
    }

    const size_t gA0 = (size_t)(bm + crow) * 1024 + cseg * 8;
    const size_t gB0 = (size_t)(bn + crow) * 1024 + cseg * 8;

#pragma unroll 1
    for (int c = 0; c < 16; c++) {
        __syncthreads();
        // ---- load 4 tiles (each: 128 rows x 64 k bf16) ----
        const size_t gk = (size_t)c * 64;
#pragma unroll
        for (int p = 0; p < 4; p++) {
            size_t ga = gA0 + gk + (size_t)p * 32 * 1024;
            size_t gb = gB0 + gk + (size_t)p * 32 * 1024;
            uint32_t so = s_sw + p * 4096;
            *(uint4*)(tp + OFF_AH + so) = *(const uint4*)(Ah + ga);
            *(uint4*)(tp + OFF_AL + so) = *(const uint4*)(Al + ga);
            *(uint4*)(tp + OFF_BH + so) = *(const uint4*)(Bh + gb);
            *(uint4*)(tp + OFF_BL + so) = *(const uint4*)(Bl + gb);
        }
        __syncthreads();

        // ---- 4 k16 steps ----
#pragma unroll
        for (int ks = 0; ks < 4; ks++) {
            const uint32_t ksb = (uint32_t)(ks * 32);
            uint32_t ah[2][4], al[2][4], bh[4][4];
#pragma unroll
            for (int mt = 0; mt < 2; mt++) {
                uint32_t ka = (ksb + a_k16) ^ a_xor[mt];
                LDSM_X4(ah[mt][0], ah[mt][1], ah[mt][2], ah[mt][3],
                        a_addr[mt] + OFF_AH + ka);
                LDSM_X4(al[mt][0], al[mt][1], al[mt][2], al[mt][3],
                        a_addr[mt] + OFF_AL + ka);
            }
#pragma unroll
            for (int p = 0; p < 4; p++) {
                uint32_t kb = (ksb + b_k16) ^ b_xor[p];
                LDSM_X4(bh[p][0], bh[p][1], bh[p][2], bh[p][3],
                        b_addr[p] + OFF_BH + kb);
            }
            // hh + lh (use bh)
#pragma unroll
            for (int mt = 0; mt < 2; mt++)
#pragma unroll
                for (int nt = 0; nt < 8; nt++) {
                    int p = nt >> 1, hf = (nt & 1) * 2;
                    MMA_BF16(acc[mt][nt], ah[mt], bh[p][hf], bh[p][hf + 1]);
                    MMA_BF16(acc[mt][nt], al[mt], bh[p][hf], bh[p][hf + 1]);
                }
            // hl (load bl, reuse ah)
            uint32_t bl[4][4];
#pragma unroll
            for (int p = 0; p < 4; p++) {
                uint32_t kb = (ksb + b_k16) ^ b_xor[p];
                LDSM_X4(bl[p][0], bl[p][1], bl[p][2], bl[p][3],
                        b_addr[p] + OFF_BL + kb);
            }
#pragma unroll
            for (int mt = 0; mt < 2; mt++)
#pragma unroll
                for (int nt = 0; nt < 8; nt++) {
                    int p = nt >> 1, hf = (nt & 1) * 2;
                    MMA_BF16(acc[mt][nt], ah[mt], bl[p][hf], bl[p][hf + 1]);
                }
        }
    }

    // ---- epilogue ----
    const int tg = lane & 3;
    const int g = lane >> 2;
    const int colbase = bn + wn * 64;

    // bias
#pragma unroll
    for (int nt = 0; nt < 8; nt++) {
        float2 bb = *(const float2*)(bias + colbase + nt * 8 + tg * 2);
#pragma unroll
        for (int mt = 0; mt < 2; mt++) {
            acc[mt][nt][0] += bb.x;
            acc[mt][nt][1] += bb.y;
            acc[mt][nt][2] += bb.x;
            acc[mt][nt][3] += bb.y;
        }
    }

    if (MODE == 0) {
        const int sec = colbase >> 10;             // 0=q 1=k 2=v
        const int h = (colbase & 1023) >> 6;
        float* buf = (sec == 0) ? g_Q : (sec == 1) ? g_K : g_V;
        if (sec < 2) {
            // fused RoPE: pair (j, j+32) lives in (nt, nt+4), same lane
#pragma unroll
            for (int mt = 0; mt < 2; mt++) {
                int m0 = bm + wm * 32 + mt * 16 + g;
#pragma unroll
                for (int nt = 0; nt < 4; nt++)
#pragma unroll
                    for (int cc = 0; cc < 4; cc++) {
                        int j = nt * 8 + tg * 2 + (cc & 1);
                        int sp = (m0 + (cc >> 1) * 8) & 2047;
                        float cf = g_cos[(sp << 5) | j];
                        float sf = g_sin[(sp << 5) | j];
                        float a1 = acc[mt][nt][cc], a2 = acc[mt][nt + 4][cc];
                        acc[mt][nt][cc]     = a1 * cf - a2 * sf;
                        acc[mt][nt + 4][cc] = a2 * cf + a1 * sf;
                    }
            }
        }
#pragma unroll
        for (int mt = 0; mt < 2; mt++) {
            int m0 = bm + wm * 32 + mt * 16 + g;
#pragma unroll
            for (int rh = 0; rh < 2; rh++) {
                int row = m0 + rh * 8;
                int b = row >> 11, sp = row & 2047;
                size_t base = (((size_t)(b * HH + h)) * SS + sp) * DD;
#pragma unroll
                for (int nt = 0; nt < 8; nt++) {
                    int d = nt * 8 + tg * 2;
                    float2 v = make_float2(acc[mt][nt][rh * 2],
                                           acc[mt][nt][rh * 2 + 1]);
                    *(float2*)(buf + base + d) = v;
                }
            }
        }
    } else {
#pragma unroll
        for (int mt = 0; mt < 2; mt++) {
            int m0 = bm + wm * 32 + mt * 16 + g;
#pragma unroll
            for (int rh = 0; rh < 2; rh++) {
                int row = m0 + rh * 8;
#pragma unroll
                for (int nt = 0; nt < 8; nt++) {
                    int col = colbase + nt * 8 + tg * 2;
                    float2 v = make_float2(acc[mt][nt][rh * 2],
                                           acc[mt][nt][rh * 2 + 1]);
                    *(float2*)(Cout + (size_t)row * EE + col) = v;
                }
            }
        }
    }
}

// ---------------------------------------------------------------------------
// Flash attention (fp32), one query row per thread, online softmax.
// ---------------------------------------------------------------------------
__global__ __launch_bounds__(128)
void flash_kernel() {
    __shared__ float Ks[32][64];
    __shared__ float Vs[32][64];
    __shared__ float Sc[128][33];

    int tid = threadIdx.x;
    int bh = blockIdx.y;
    int q = blockIdx.x * 128 + tid;
    size_t rowbase = ((size_t)bh * SS + q) * DD;

    float Qr[64];
#pragma unroll
    for (int d = 0; d < 64; d += 4) {
        float4 vv = *(const float4*)(g_Q + rowbase + d);
        Qr[d] = vv.x; Qr[d + 1] = vv.y; Qr[d + 2] = vv.z; Qr[d + 3] = vv.w;
    }

    float O[64];
#pragma unroll
    for (int d = 0; d < 64; d++) O[d] = 0.f;
    float m = -INFINITY, l = 0.f;

    int kend = blockIdx.x * 128 + 128;
    size_t kvbase = (size_t)bh * SS * DD;

    for (int k0 = 0; k0 < kend; k0 += 32) {
#pragma unroll
        for (int i = 0; i < 4; i++) {
            int fi = (tid + i * 128) * 4;
            *(float4*)((float*)Ks + fi) =
                *(const float4*)(g_K + kvbase + (size_t)k0 * DD + fi);
            *(float4*)((float*)Vs + fi) =
                *(const float4*)(g_V + kvbase + (size_t)k0 * DD + fi);
        }
        __syncthreads();

        float tmax = -INFINITY;
#pragma unroll 4
        for (int k = 0; k < 32; k++) {
            const float4* kr = (const float4*)&Ks[k][0];
            float a0 = 0.f, a1 = 0.f, a2 = 0.f, a3 = 0.f;
#pragma unroll
            for (int i = 0; i < 16; i += 4) {
                float4 c0 = kr[i], c1 = kr[i + 1], c2 = kr[i + 2], c3 = kr[i + 3];
                a0 += Qr[4*i+0]*c0.x + Qr[4*i+1]*c0.y + Qr[4*i+2]*c0.z + Qr[4*i+3]*c0.w;
                a1 += Qr[4*i+4]*c1.x + Qr[4*i+5]*c1.y + Qr[4*i+6]*c1.z + Qr[4*i+7]*c1.w;
                a2 += Qr[4*i+8]*c2.x + Qr[4*i+9]*c2.y + Qr[4*i+10]*c2.z + Qr[4*i+11]*c2.w;
                a3 += Qr[4*i+12]*c3.x + Qr[4*i+13]*c3.y + Qr[4*i+14]*c3.z + Qr[4*i+15]*c3.w;
            }
            float s = (a0 + a1) + (a2 + a3);
            s *= 0.125f;
            if (k0 + k > q) s = -1e30f;
            Sc[tid][k] = s;
            tmax = fmaxf(tmax, s);
        }

        float mn = fmaxf(m, tmax);
        float corr = __expf(m - mn);
        l *= corr;
#pragma unroll
        for (int d = 0; d < 64; d++) O[d] *= corr;

#pragma unroll 2
        for (int k = 0; k < 32; k++) {
            float p = __expf(Sc[tid][k] - mn);
            l += p;
#pragma unroll
            for (int d = 0; d < 64; d += 4) {
                float4 vv = *(const float4*)&Vs[k][d];
                O[d]     += p * vv.x;
                O[d + 1] += p * vv.y;
                O[d + 2] += p * vv.z;
                O[d + 3] += p * vv.w;
            }
        }
        m = mn;
        __syncthreads();
    }

    float inv_l = 1.f / l;
    int b = bh >> 4, h = bh & 15;
    size_t obase = ((size_t)(b * SS + q)) * EE + h * DD;
#pragma unroll
    for (int d = 0; d < 64; d += 4) {
        float4 vv;
        vv.x = O[d] * inv_l;
        vv.y = O[d + 1] * inv_l;
        vv.z = O[d + 2] * inv_l;
        vv.w = O[d + 3] * inv_l;
        *(float4*)(g_ctx + obase + d) = vv;
    }
}

// ---------------------------------------------------------------------------
// Launch
// ---------------------------------------------------------------------------
extern "C" void kernel_launch(void* const* d_in, const int* in_sizes, int n_in,
                              void* d_out, int out_size) {
    const float* x      = (const float*)d_in[0];   // [4,2048,1024]
    const float* w_qkv  = (const float*)d_in[1];   // [1024,3072]
    const float* b_qkv  = (const float*)d_in[2];   // [3072]
    const float* w_proj = (const float*)d_in[3];   // [1024,1024]
    const float* b_proj = (const float*)d_in[4];   // [1024]
    float* out = (float*)d_out;                    // [4,2048,1024]

    cudaFuncSetAttribute(gemm_mma<0>, cudaFuncAttributeMaxDynamicSharedMemorySize,
                         GEMM_SMEM_BYTES);
    cudaFuncSetAttribute(gemm_mma<1>, cudaFuncAttributeMaxDynamicSharedMemorySize,
                         GEMM_SMEM_BYTES);

    // 1) RoPE table
    rope_table_kernel<<<(SS * 32 + 255) / 256, 256>>>();

    // 2) Split x; transpose+split weights
    split_kernel<<<(MROWS * EE / 4 + 255) / 256, 256>>>(x, 0);
    {
        dim3 blk(32, 8);
        transpose_split_kernel<<<dim3(3072 / 32, 1024 / 32), blk>>>(w_qkv, 1024, 3072, 0);
        transpose_split_kernel<<<dim3(1024 / 32, 1024 / 32), blk>>>(w_proj, 1024, 1024, 1);
    }

    // 3) QKV GEMM (HMMA) -> Q/K/V head layout with fused bias+RoPE
    gemm_mma<0><<<dim3(24, 64), 256, GEMM_SMEM_BYTES>>>(b_qkv, nullptr);

    // 4) Attention
    flash_kernel<<<dim3(SS / 128, BB * HH), 128>>>();

    // 5) Split ctx; output projection (HMMA) -> d_out
    split_kernel<<<(MROWS * EE / 4 + 255) / 256, 256>>>(nullptr, 1);
    gemm_mma<1><<<dim3(8, 64), 256, GEMM_SMEM_BYTES>>>(b_proj, out);
}

// round 4
// speedup vs baseline: 3.5790x; 2.1846x over previous
#include <cuda_runtime.h>
#include <cuda_bf16.h>
#include <math.h>
#include <stdint.h>

// Problem constants
#define BB 4
#define SS 2048
#define EE 1024
#define HH 16
#define DD 64
#define MROWS (BB*SS)          // 8192

// ---------------------------------------------------------------------------
// Scratch (device globals -- no allocation allowed)
// ---------------------------------------------------------------------------
__device__ float g_cos[SS*32];
__device__ float g_sin[SS*32];

__device__ __nv_bfloat16 g_xh[MROWS*EE],   g_xl[MROWS*EE];       // x split
__device__ __nv_bfloat16 g_ch[MROWS*EE],   g_cl[MROWS*EE];       // ctx split
__device__ __nv_bfloat16 g_wqh[3072*1024], g_wql[3072*1024];     // w_qkv^T
__device__ __nv_bfloat16 g_wph[1024*1024], g_wpl[1024*1024];     // w_proj^T

// Q/K/V in [bh][s][d] layout, bf16 hi/lo (Q pre-scaled by 1/sqrt(D))
__device__ __nv_bfloat16 g_Qh[BB*HH*SS*DD], g_Ql[BB*HH*SS*DD];
__device__ __nv_bfloat16 g_Kh[BB*HH*SS*DD], g_Kl[BB*HH*SS*DD];
__device__ __nv_bfloat16 g_Vh[BB*HH*SS*DD], g_Vl[BB*HH*SS*DD];

// ---------------------------------------------------------------------------
// PTX helpers (baseline PTX only: ldmatrix + mma.sync, legal on compute_103)
// ---------------------------------------------------------------------------
__device__ __forceinline__ uint32_t smem_u32(const void* p) {
    uint32_t a;
    asm("{ .reg .u64 t; cvta.to.shared.u64 t, %1; cvt.u32.u64 %0, t; }"
        : "=r"(a) : "l"(p));
    return a;
}

#define LDSM_X4(r0, r1, r2, r3, addr) \
    asm volatile("ldmatrix.sync.aligned.m8n8.x4.shared.b16 {%0,%1,%2,%3}, [%4];" \
        : "=r"(r0), "=r"(r1), "=r"(r2), "=r"(r3) : "r"(addr))

#define LDSM_X4_T(r0, r1, r2, r3, addr) \
    asm volatile("ldmatrix.sync.aligned.m8n8.x4.trans.shared.b16 {%0,%1,%2,%3}, [%4];" \
        : "=r"(r0), "=r"(r1), "=r"(r2), "=r"(r3) : "r"(addr))

#define MMA_BF16(c, a, b0, b1) \
    asm volatile("mma.sync.aligned.m16n8k16.row.col.f32.bf16.bf16.f32 " \
        "{%0,%1,%2,%3}, {%4,%5,%6,%7}, {%8,%9}, {%0,%1,%2,%3};" \
        : "+f"((c)[0]), "+f"((c)[1]), "+f"((c)[2]), "+f"((c)[3]) \
        : "r"((a)[0]), "r"((a)[1]), "r"((a)[2]), "r"((a)[3]), \
          "r"(b0), "r"(b1))

// bf16 hi/lo split of two floats, packed as bf16x2 words (x -> low half)
__device__ __forceinline__ void bfsplit2(float x, float y,
                                         uint32_t& hi, uint32_t& lo) {
    __nv_bfloat16 hx = __float2bfloat16(x);
    __nv_bfloat16 hy = __float2bfloat16(y);
    __nv_bfloat16 lx = __float2bfloat16(x - __bfloat162float(hx));
    __nv_bfloat16 ly = __float2bfloat16(y - __bfloat162float(hy));
    __nv_bfloat162 h2 = __halves2bfloat162(hx, hy);
    __nv_bfloat162 l2 = __halves2bfloat162(lx, ly);
    hi = *reinterpret_cast<uint32_t*>(&h2);
    lo = *reinterpret_cast<uint32_t*>(&l2);
}

// ---------------------------------------------------------------------------
// RoPE table (double precision: angle up to ~2047 rad)
// ---------------------------------------------------------------------------
__global__ void rope_table_kernel() {
    int i = blockIdx.x * blockDim.x + threadIdx.x;
    if (i >= SS * 32) return;
    int s = i >> 5;
    int j = i & 31;
    double inv = pow(10000.0, -(double)(2 * j) / 64.0);
    double a = (double)s * inv;
    g_cos[i] = (float)cos(a);
    g_sin[i] = (float)sin(a);
}

// ---------------------------------------------------------------------------
// Split fp32 x -> bf16 hi/lo
// ---------------------------------------------------------------------------
__global__ void split_kernel(const float* __restrict__ in) {
    int i = blockIdx.x * blockDim.x + threadIdx.x;
    if (i >= MROWS * EE / 4) return;
    float4 v = ((const float4*)in)[i];
    uint32_t h0, l0, h1, l1;
    bfsplit2(v.x, v.y, h0, l0);
    bfsplit2(v.z, v.w, h1, l1);
    ((uint2*)g_xh)[i] = make_uint2(h0, h1);
    ((uint2*)g_xl)[i] = make_uint2(l0, l1);
}

// ---------------------------------------------------------------------------
// Transpose + split: in [R][C] fp32 -> out [C][R] bf16 hi/lo
// ---------------------------------------------------------------------------
__global__ void transpose_split_kernel(const float* __restrict__ in,
                                       int R, int C, int which) {
    __shared__ float t[32][33];
    __nv_bfloat16* oh = which ? g_wph : g_wqh;
    __nv_bfloat16* ol = which ? g_wpl : g_wql;
    int bx = blockIdx.x * 32, by = blockIdx.y * 32;
#pragma unroll
    for (int i = threadIdx.y; i < 32; i += 8)
        t[i][threadIdx.x] = in[(size_t)(by + i) * C + bx + threadIdx.x];
    __syncthreads();
#pragma unroll
    for (int i = threadIdx.y; i < 32; i += 8) {
        float v = t[threadIdx.x][i];
        __nv_bfloat16 h = __float2bfloat16(v);
        __nv_bfloat16 l = __float2bfloat16(v - __bfloat162float(h));
        size_t idx = (size_t)(bx + i) * R + by + threadIdx.x;
        oh[idx] = h;
        ol[idx] = l;
    }
}

// ---------------------------------------------------------------------------
// HMMA GEMM (bf16 hi/lo split, fp32 acc).  CTA 128x128, K-chunk 64.
// MODE 0: A=g_xh/xl, B=g_wqh/wql; epi = bias + RoPE (+1/8 scale on Q),
//         split to bf16 hi/lo, scatter to g_Qh/Ql/Kh/Kl/Vh/Vl.
// MODE 1: A=g_ch/cl, B=g_wph/wpl; epi = bias -> Cout fp32.
// ---------------------------------------------------------------------------
#define OFF_AH 0
#define OFF_AL 16384
#define OFF_BH 32768
#define OFF_BL 49152
#define GEMM_SMEM_BYTES (4*16384 + 1024)

template <int MODE>
__global__ __launch_bounds__(256, 2)
void gemm_mma(const float* __restrict__ bias, float* __restrict__ Cout) {
    extern __shared__ char smem_raw[];
    const uint32_t sb = smem_u32(smem_raw);
    const uint32_t tiles = (sb + 1023u) & ~1023u;
    char* tp = smem_raw + (tiles - sb);

    const __nv_bfloat16* Ah = (MODE == 0) ? g_xh : g_ch;
    const __nv_bfloat16* Al = (MODE == 0) ? g_xl : g_cl;
    const __nv_bfloat16* Bh = (MODE == 0) ? g_wqh : g_wph;
    const __nv_bfloat16* Bl = (MODE == 0) ? g_wql : g_wpl;

    const int tid = threadIdx.x;
    const int lane = tid & 31;
    const int warp = tid >> 5;
    const int wm = warp >> 1;
    const int wn = warp & 1;
    const int bm = blockIdx.y * 128;
    const int bn = blockIdx.x * 128;

    float acc[2][8][4];
#pragma unroll
    for (int mt = 0; mt < 2; mt++)
#pragma unroll
        for (int nt = 0; nt < 8; nt++)
#pragma unroll
            for (int c = 0; c < 4; c++) acc[mt][nt][c] = 0.f;

    const int crow = tid >> 3;
    const int cseg = tid & 7;
    const uint32_t s_off = (uint32_t)(crow * 128 + cseg * 16);
    const uint32_t s_sw = s_off ^ ((s_off >> 3) & 0x70);

    const int mat = lane >> 3;
    const int rr = lane & 7;
    const int a_row_base = wm * 32 + (mat & 1) * 8 + rr;
    const uint32_t a_k16 = (uint32_t)((mat >> 1) * 16);
    const int b_row_base = wn * 64 + (mat >> 1) * 8 + rr;
    const uint32_t b_k16 = (uint32_t)((mat & 1) * 16);

    uint32_t a_addr[2], a_xor[2], b_addr[4], b_xor[4];
#pragma unroll
    for (int mt = 0; mt < 2; mt++) {
        int row = a_row_base + mt * 16;
        a_addr[mt] = tiles + (uint32_t)(row * 128);
        a_xor[mt] = (uint32_t)((row & 7) << 4);
    }
#pragma unroll
    for (int p = 0; p < 4; p++) {
        int row = b_row_base + p * 16;
        b_addr[p] = tiles + (uint32_t)(row * 128);
        b_xor[p] = (uint32_t)((row & 7) << 4);
    }

    const size_t gA0 = (size_t)(bm + crow) * 1024 + cseg * 8;
    const size_t gB0 = (size_t)(bn + crow) * 1024 + cseg * 8;

#pragma unroll 1
    for (int c = 0; c < 16; c++) {
        __syncthreads();
        const size_t gk = (size_t)c * 64;
#pragma unroll
        for (int p = 0; p < 4; p++) {
            size_t ga = gA0 + gk + (size_t)p * 32 * 1024;
            size_t gb = gB0 + gk + (size_t)p * 32 * 1024;
            uint32_t so = s_sw + p * 4096;
            *(uint4*)(tp + OFF_AH + so) = *(const uint4*)(Ah + ga);
            *(uint4*)(tp + OFF_AL + so) = *(const uint4*)(Al + ga);
            *(uint4*)(tp + OFF_BH + so) = *(const uint4*)(Bh + gb);
            *(uint4*)(tp + OFF_BL + so) = *(const uint4*)(Bl + gb);
        }
        __syncthreads();

#pragma unroll
        for (int ks = 0; ks < 4; ks++) {
            const uint32_t ksb = (uint32_t)(ks * 32);
            uint32_t ah[2][4], al[2][4], bh[4][4];
#pragma unroll
            for (int mt = 0; mt < 2; mt++) {
                uint32_t ka = (ksb + a_k16) ^ a_xor[mt];
                LDSM_X4(ah[mt][0], ah[mt][1], ah[mt][2], ah[mt][3],
                        a_addr[mt] + OFF_AH + ka);
                LDSM_X4(al[mt][0], al[mt][1], al[mt][2], al[mt][3],
                        a_addr[mt] + OFF_AL + ka);
            }
#pragma unroll
            for (int p = 0; p < 4; p++) {
                uint32_t kb = (ksb + b_k16) ^ b_xor[p];
                LDSM_X4(bh[p][0], bh[p][1], bh[p][2], bh[p][3],
                        b_addr[p] + OFF_BH + kb);
            }
#pragma unroll
            for (int mt = 0; mt < 2; mt++)
#pragma unroll
                for (int nt = 0; nt < 8; nt++) {
                    int p = nt >> 1, hf = (nt & 1) * 2;
                    MMA_BF16(acc[mt][nt], ah[mt], bh[p][hf], bh[p][hf + 1]);
                    MMA_BF16(acc[mt][nt], al[mt], bh[p][hf], bh[p][hf + 1]);
                }
            uint32_t bl[4][4];
#pragma unroll
            for (int p = 0; p < 4; p++) {
                uint32_t kb = (ksb + b_k16) ^ b_xor[p];
                LDSM_X4(bl[p][0], bl[p][1], bl[p][2], bl[p][3],
                        b_addr[p] + OFF_BL + kb);
            }
#pragma unroll
            for (int mt = 0; mt < 2; mt++)
#pragma unroll
                for (int nt = 0; nt < 8; nt++) {
                    int p = nt >> 1, hf = (nt & 1) * 2;
                    MMA_BF16(acc[mt][nt], ah[mt], bl[p][hf], bl[p][hf + 1]);
                }
        }
    }

    // ---- epilogue ----
    const int tg = lane & 3;
    const int g = lane >> 2;
    const int colbase = bn + wn * 64;

#pragma unroll
    for (int nt = 0; nt < 8; nt++) {
        float2 bb = *(const float2*)(bias + colbase + nt * 8 + tg * 2);
#pragma unroll
        for (int mt = 0; mt < 2; mt++) {
            acc[mt][nt][0] += bb.x;
            acc[mt][nt][1] += bb.y;
            acc[mt][nt][2] += bb.x;
            acc[mt][nt][3] += bb.y;
        }
    }

    if (MODE == 0) {
        const int sec = colbase >> 10;             // 0=q 1=k 2=v
        const int h = (colbase & 1023) >> 6;
        __nv_bfloat16* bufh = (sec == 0) ? g_Qh : (sec == 1) ? g_Kh : g_Vh;
        __nv_bfloat16* bufl = (sec == 0) ? g_Ql : (sec == 1) ? g_Kl : g_Vl;
        if (sec < 2) {
            // fused RoPE: pair (j, j+32) lives in (nt, nt+4), same lane
#pragma unroll
            for (int mt = 0; mt < 2; mt++) {
                int m0 = bm + wm * 32 + mt * 16 + g;
#pragma unroll
                for (int nt = 0; nt < 4; nt++)
#pragma unroll
                    for (int cc = 0; cc < 4; cc++) {
                        int j = nt * 8 + tg * 2 + (cc & 1);
                        int sp = (m0 + (cc >> 1) * 8) & 2047;
                        float cf = g_cos[(sp << 5) | j];
                        float sf = g_sin[(sp << 5) | j];
                        float a1 = acc[mt][nt][cc], a2 = acc[mt][nt + 4][cc];
                        acc[mt][nt][cc]     = a1 * cf - a2 * sf;
                        acc[mt][nt + 4][cc] = a2 * cf + a1 * sf;
                    }
            }
        }
        if (sec == 0) {     // fold 1/sqrt(D) into Q
#pragma unroll
            for (int mt = 0; mt < 2; mt++)
#pragma unroll
                for (int nt = 0; nt < 8; nt++)
#pragma unroll
                    for (int cc = 0; cc < 4; cc++) acc[mt][nt][cc] *= 0.125f;
        }
#pragma unroll
        for (int mt = 0; mt < 2; mt++) {
            int m0 = bm + wm * 32 + mt * 16 + g;
#pragma unroll
            for (int rh = 0; rh < 2; rh++) {
                int row = m0 + rh * 8;
                int b = row >> 11, sp = row & 2047;
                size_t base = (((size_t)(b * HH + h)) * SS + sp) * DD;
#pragma unroll
                for (int nt = 0; nt < 8; nt++) {
                    int d = nt * 8 + tg * 2;
                    uint32_t hi, lo;
                    bfsplit2(acc[mt][nt][rh * 2], acc[mt][nt][rh * 2 + 1], hi, lo);
                    *(uint32_t*)(bufh + base + d) = hi;
                    *(uint32_t*)(bufl + base + d) = lo;
                }
            }
        }
    } else {
#pragma unroll
        for (int mt = 0; mt < 2; mt++) {
            int m0 = bm + wm * 32 + mt * 16 + g;
#pragma unroll
            for (int rh = 0; rh < 2; rh++) {
                int row = m0 + rh * 8;
#pragma unroll
                for (int nt = 0; nt < 8; nt++) {
                    int col = colbase + nt * 8 + tg * 2;
                    float2 v = make_float2(acc[mt][nt][rh * 2],
                                           acc[mt][nt][rh * 2 + 1]);
                    *(float2*)(Cout + (size_t)row * EE + col) = v;
                }
            }
        }
    }
}

// ---------------------------------------------------------------------------
// Tensor-core flash attention (bf16 hi/lo split, fp32 softmax).
// CTA: 128 q rows of one (b,h), 8 warps x 16 rows. 64-key tiles.
// Writes ctx bf16 hi/lo directly to g_ch/g_cl in [b*S+s][e] layout.
// ---------------------------------------------------------------------------
#define FQH 0
#define FQL 16384
#define FKH 32768
#define FKL 40960
#define FVH 49152
#define FVL 57344
#define FLASH_SMEM_BYTES (65536 + 1024)

__global__ __launch_bounds__(256, 1)
void flash_mma() {
    extern __shared__ char smem_raw[];
    const uint32_t sb = smem_u32(smem_raw);
    const uint32_t tiles = (sb + 1023u) & ~1023u;
    char* tp = smem_raw + (tiles - sb);

    const int tid = threadIdx.x;
    const int lane = tid & 31;
    const int warp = tid >> 5;
    const int bh = blockIdx.y;
    const int qb = blockIdx.x;
    const int q0 = qb * 128;
    const size_t qkv_base = (size_t)bh * SS * DD;

    // ---- load Q tile (128 x 64) hi/lo into smem ----
#pragma unroll
    for (int i = 0; i < 4; i++) {
        int sidx = tid + i * 256;           // 0..1023
        int row = sidx >> 3, sg = sidx & 7;
        uint32_t so = (uint32_t)(row * 128 + sg * 16);
        uint32_t sw = so ^ ((uint32_t)(row & 7) << 4);
        size_t go = qkv_base + (size_t)(q0 + row) * DD + sg * 8;
        *(uint4*)(tp + FQH + sw) = *(const uint4*)(g_Qh + go);
        *(uint4*)(tp + FQL + sw) = *(const uint4*)(g_Ql + go);
    }
    __syncthreads();

    const int mat = lane >> 3;
    const int rr = lane & 7;
    const int g = lane >> 2;
    const int tg = lane & 3;

    // ---- Q fragments (A operand), 4 k16 steps over d, hi+lo ----
    uint32_t aqh[4][4], aql[4][4];
    {
        int row = warp * 16 + (mat & 1) * 8 + rr;
        uint32_t roff = (uint32_t)(row * 128);
        uint32_t x = (uint32_t)((row & 7) << 4);
#pragma unroll
        for (int ks = 0; ks < 4; ks++) {
            uint32_t col = (uint32_t)(ks * 32 + (mat >> 1) * 16);
            LDSM_X4(aqh[ks][0], aqh[ks][1], aqh[ks][2], aqh[ks][3],
                    tiles + FQH + roff + (col ^ x));
            LDSM_X4(aql[ks][0], aql[ks][1], aql[ks][2], aql[ks][3],
                    tiles + FQL + roff + (col ^ x));
        }
    }

    float O[8][4];
#pragma unroll
    for (int nt = 0; nt < 8; nt++)
#pragma unroll
        for (int c = 0; c < 4; c++) O[nt][c] = 0.f;
    float mrow[2] = {-INFINITY, -INFINITY};
    float lrow[2] = {0.f, 0.f};

    // K fragment addressing (B operand, n = keys)
    const int k_rowb = (mat >> 1) * 8 + rr;
    const uint32_t k_k16 = (uint32_t)((mat & 1) * 16);
    // V^T fragment addressing (trans: rows = keys, cols = d)
    const int v_rowb = (mat & 1) * 8 + rr;
    const uint32_t v_d16 = (uint32_t)((mat >> 1) * 16);

    const int ktiles = 2 * qb + 2;
    const int warp_row_min = q0 + warp * 16;

#pragma unroll 1
    for (int kt = 0; kt < ktiles; kt++) {
        const int k0 = kt * 64;
        __syncthreads();
        // ---- load K/V tile (64 x 64) hi/lo ----
#pragma unroll
        for (int i = 0; i < 2; i++) {
            int sidx = tid + i * 256;       // 0..511
            int row = sidx >> 3, sg = sidx & 7;
            uint32_t so = (uint32_t)(row * 128 + sg * 16);
            uint32_t sw = so ^ ((uint32_t)(row & 7) << 4);
            size_t go = qkv_base + (size_t)(k0 + row) * DD + sg * 8;
            *(uint4*)(tp + FKH + sw) = *(const uint4*)(g_Kh + go);
            *(uint4*)(tp + FKL + sw) = *(const uint4*)(g_Kl + go);
            *(uint4*)(tp + FVH + sw) = *(const uint4*)(g_Vh + go);
            *(uint4*)(tp + FVL + sw) = *(const uint4*)(g_Vl + go);
        }
        __syncthreads();

        // ---- scores S = Q K^T (hh + lh + hl) ----
        float s[8][4];
#pragma unroll
        for (int nt = 0; nt < 8; nt++)
#pragma unroll
            for (int c = 0; c < 4; c++) s[nt][c] = 0.f;

#pragma unroll
        for (int np = 0; np < 4; np++) {
            int row = np * 16 + k_rowb;
            uint32_t roff = (uint32_t)(row * 128);
            uint32_t x = (uint32_t)((row & 7) << 4);
#pragma unroll
            for (int ks = 0; ks < 4; ks++) {
                uint32_t col = (uint32_t)(ks * 32) + k_k16;
                uint32_t kh[4], kl[4];
                LDSM_X4(kh[0], kh[1], kh[2], kh[3],
                        tiles + FKH + roff + (col ^ x));
                LDSM_X4(kl[0], kl[1], kl[2], kl[3],
                        tiles + FKL + roff + (col ^ x));
                MMA_BF16(s[2*np],   aqh[ks], kh[0], kh[1]);
                MMA_BF16(s[2*np],   aql[ks], kh[0], kh[1]);
                MMA_BF16(s[2*np],   aqh[ks], kl[0], kl[1]);
                MMA_BF16(s[2*np+1], aqh[ks], kh[2], kh[3]);
                MMA_BF16(s[2*np+1], aql[ks], kh[2], kh[3]);
                MMA_BF16(s[2*np+1], aqh[ks], kl[2], kl[3]);
            }
        }

        // ---- causal mask (only tiles reaching the diagonal) ----
        if (k0 + 63 > warp_row_min) {
#pragma unroll
            for (int nt = 0; nt < 8; nt++)
#pragma unroll
                for (int c = 0; c < 4; c++) {
                    int col = k0 + nt * 8 + tg * 2 + (c & 1);
                    int rw = warp_row_min + g + (c >> 1) * 8;
                    if (col > rw) s[nt][c] = -1e30f;
                }
        }

        // ---- online softmax ----
#pragma unroll
        for (int rh = 0; rh < 2; rh++) {
            float vm = -INFINITY;
#pragma unroll
            for (int nt = 0; nt < 8; nt++)
                vm = fmaxf(vm, fmaxf(s[nt][rh*2], s[nt][rh*2+1]));
            vm = fmaxf(vm, __shfl_xor_sync(0xffffffffu, vm, 1));
            vm = fmaxf(vm, __shfl_xor_sync(0xffffffffu, vm, 2));
            float mn = fmaxf(mrow[rh], vm);
            float sc = __expf(mrow[rh] - mn);
            mrow[rh] = mn;
            lrow[rh] *= sc;
            float psum = 0.f;
#pragma unroll
            for (int nt = 0; nt < 8; nt++) {
                float p0 = __expf(s[nt][rh*2]   - mn);
                float p1 = __expf(s[nt][rh*2+1] - mn);
                s[nt][rh*2] = p0;
                s[nt][rh*2+1] = p1;
                psum += p0 + p1;
                O[nt][rh*2]   *= sc;
                O[nt][rh*2+1] *= sc;
            }
            lrow[rh] += psum;
        }

        // ---- O += P V (hh + lh + hl) ----
#pragma unroll
        for (int ks = 0; ks < 4; ks++) {        // key k16 blocks
            uint32_t ph[4], pl[4];
            bfsplit2(s[2*ks][0],   s[2*ks][1],   ph[0], pl[0]);
            bfsplit2(s[2*ks][2],   s[2*ks][3],   ph[1], pl[1]);
            bfsplit2(s[2*ks+1][0], s[2*ks+1][1], ph[2], pl[2]);
            bfsplit2(s[2*ks+1][2], s[2*ks+1][3], ph[3], pl[3]);

            int row = ks * 16 + v_rowb;
            uint32_t roff = (uint32_t)(row * 128);
            uint32_t x = (uint32_t)((row & 7) << 4);
#pragma unroll
            for (int dp = 0; dp < 4; dp++) {
                uint32_t col = (uint32_t)(dp * 32) + v_d16;
                uint32_t vh[4], vl[4];
                LDSM_X4_T(vh[0], vh[1], vh[2], vh[3],
                          tiles + FVH + roff + (col ^ x));
                LDSM_X4_T(vl[0], vl[1], vl[2], vl[3],
                          tiles + FVL + roff + (col ^ x));
                MMA_BF16(O[2*dp],   ph, vh[0], vh[1]);
                MMA_BF16(O[2*dp],   pl, vh[0], vh[1]);
                MMA_BF16(O[2*dp],   ph, vl[0], vl[1]);
                MMA_BF16(O[2*dp+1], ph, vh[2], vh[3]);
                MMA_BF16(O[2*dp+1], pl, vh[2], vh[3]);
                MMA_BF16(O[2*dp+1], ph, vl[2], vl[3]);
            }
        }
    }

    // ---- epilogue: 1/l, split to bf16 hi/lo, write ctx ----
    float inv[2];
#pragma unroll
    for (int rh = 0; rh < 2; rh++) {
        float l = lrow[rh];
        l += __shfl_xor_sync(0xffffffffu, l, 1);
        l += __shfl_xor_sync(0xffffffffu, l, 2);
        inv[rh] = 1.f / l;
    }
    const int b = bh >> 4, h = bh & 15;
#pragma unroll
    for (int rh = 0; rh < 2; rh++) {
        int sp = q0 + warp * 16 + g + rh * 8;
        size_t base = ((size_t)(b * SS + sp)) * EE + h * DD;
#pragma unroll
        for (int nt = 0; nt < 8; nt++) {
            int d = nt * 8 + tg * 2;
            uint32_t hi, lo;
            bfsplit2(O[nt][rh*2] * inv[rh], O[nt][rh*2+1] * inv[rh], hi, lo);
            *(uint32_t*)(g_ch + base + d) = hi;
            *(uint32_t*)(g_cl + base + d) = lo;
        }
    }
}

// ---------------------------------------------------------------------------
// Launch
// ---------------------------------------------------------------------------
extern "C" void kernel_launch(void* const* d_in, const int* in_sizes, int n_in,
                              void* d_out, int out_size) {
    const float* x      = (const float*)d_in[0];   // [4,2048,1024]
    const float* w_qkv  = (const float*)d_in[1];   // [1024,3072]
    const float* b_qkv  = (const float*)d_in[2];   // [3072]
    const float* w_proj = (const float*)d_in[3];   // [1024,1024]
    const float* b_proj = (const float*)d_in[4];   // [1024]
    float* out = (float*)d_out;                    // [4,2048,1024]

    cudaFuncSetAttribute(gemm_mma<0>, cudaFuncAttributeMaxDynamicSharedMemorySize,
                         GEMM_SMEM_BYTES);
    cudaFuncSetAttribute(gemm_mma<1>, cudaFuncAttributeMaxDynamicSharedMemorySize,
                         GEMM_SMEM_BYTES);
    cudaFuncSetAttribute(flash_mma, cudaFuncAttributeMaxDynamicSharedMemorySize,
                         FLASH_SMEM_BYTES);

    // 1) RoPE table
    rope_table_kernel<<<(SS * 32 + 255) / 256, 256>>>();

    // 2) Split x; transpose+split weights
    split_kernel<<<(MROWS * EE / 4 + 255) / 256, 256>>>(x);
    {
        dim3 blk(32, 8);
        transpose_split_kernel<<<dim3(3072 / 32, 1024 / 32), blk>>>(w_qkv, 1024, 3072, 0);
        transpose_split_kernel<<<dim3(1024 / 32, 1024 / 32), blk>>>(w_proj, 1024, 1024, 1);
    }

    // 3) QKV GEMM (HMMA) -> bf16 hi/lo Q/K/V with fused bias+RoPE+scale
    gemm_mma<0><<<dim3(24, 64), 256, GEMM_SMEM_BYTES>>>(b_qkv, nullptr);

    // 4) Tensor-core flash attention -> bf16 hi/lo ctx
    flash_mma<<<dim3(SS / 128, BB * HH), 256, FLASH_SMEM_BYTES>>>();

    // 5) Output projection (HMMA) -> d_out
    gemm_mma<1><<<dim3(8, 64), 256, GEMM_SMEM_BYTES>>>(b_proj, out);
}

// round 5
// speedup vs baseline: 5.7608x; 1.6096x over previous
#include <cuda_runtime.h>
#include <cuda_fp16.h>
#include <math.h>
#include <stdint.h>

// Problem constants
#define BB 4
#define SS 2048
#define EE 1024
#define HH 16
#define DD 64
#define MROWS (BB*SS)          // 8192

// ---------------------------------------------------------------------------
// Scratch (device globals -- no allocation allowed)
// ---------------------------------------------------------------------------
__device__ float g_cos[SS*32];
__device__ float g_sin[SS*32];

__device__ __half g_xh[MROWS*EE], g_xl[MROWS*EE];      // x split hi/lo
__device__ __half g_ch[MROWS*EE], g_cl[MROWS*EE];      // ctx split hi/lo
__device__ __half g_wqh[3072*1024];                    // w_qkv^T fp16
__device__ __half g_wph[1024*1024];                    // w_proj^T fp16

// Q hi/lo (pre-scaled by 1/sqrt(D)); K, V single fp16. [bh][s][d]
__device__ __half g_Qh[BB*HH*SS*DD], g_Ql[BB*HH*SS*DD];
__device__ __half g_Kh[BB*HH*SS*DD];
__device__ __half g_Vh[BB*HH*SS*DD];

// ---------------------------------------------------------------------------
// PTX helpers (baseline PTX: ldmatrix + mma.sync + cp.async, sm_80-era)
// ---------------------------------------------------------------------------
__device__ __forceinline__ uint32_t smem_u32(const void* p) {
    uint32_t a;
    asm("{ .reg .u64 t; cvta.to.shared.u64 t, %1; cvt.u32.u64 %0, t; }"
        : "=r"(a) : "l"(p));
    return a;
}

#define LDSM_X4(r0, r1, r2, r3, addr) \
    asm volatile("ldmatrix.sync.aligned.m8n8.x4.shared.b16 {%0,%1,%2,%3}, [%4];" \
        : "=r"(r0), "=r"(r1), "=r"(r2), "=r"(r3) : "r"(addr))

#define LDSM_X4_T(r0, r1, r2, r3, addr) \
    asm volatile("ldmatrix.sync.aligned.m8n8.x4.trans.shared.b16 {%0,%1,%2,%3}, [%4];" \
        : "=r"(r0), "=r"(r1), "=r"(r2), "=r"(r3) : "r"(addr))

#define MMA_F16(c, a, b0, b1) \
    asm volatile("mma.sync.aligned.m16n8k16.row.col.f32.f16.f16.f32 " \
        "{%0,%1,%2,%3}, {%4,%5,%6,%7}, {%8,%9}, {%0,%1,%2,%3};" \
        : "+f"((c)[0]), "+f"((c)[1]), "+f"((c)[2]), "+f"((c)[3]) \
        : "r"((a)[0]), "r"((a)[1]), "r"((a)[2]), "r"((a)[3]), \
          "r"(b0), "r"(b1))

#define CP_ASYNC16(dst, src) \
    asm volatile("cp.async.cg.shared.global [%0], [%1], 16;" \
        :: "r"(dst), "l"(src) : "memory")
#define CP_COMMIT() asm volatile("cp.async.commit_group;" ::: "memory")
#define CP_WAIT1() asm volatile("cp.async.wait_group 1;" ::: "memory")
#define CP_WAIT0() asm volatile("cp.async.wait_group 0;" ::: "memory")

// fp16 hi/lo split of two floats, packed as half2 words (x -> low half)
__device__ __forceinline__ void hsplit2(float x, float y,
                                        uint32_t& hi, uint32_t& lo) {
    __half hx = __float2half(x);
    __half hy = __float2half(y);
    __half lx = __float2half(x - __half2float(hx));
    __half ly = __float2half(y - __half2float(hy));
    __half2 h2 = __halves2half2(hx, hy);
    __half2 l2 = __halves2half2(lx, ly);
    hi = *reinterpret_cast<uint32_t*>(&h2);
    lo = *reinterpret_cast<uint32_t*>(&l2);
}

// ---------------------------------------------------------------------------
// RoPE table (double precision: angle up to ~2047 rad)
// ---------------------------------------------------------------------------
__global__ void rope_table_kernel() {
    int i = blockIdx.x * blockDim.x + threadIdx.x;
    if (i >= SS * 32) return;
    int s = i >> 5;
    int j = i & 31;
    double inv = pow(10000.0, -(double)(2 * j) / 64.0);
    double a = (double)s * inv;
    g_cos[i] = (float)cos(a);
    g_sin[i] = (float)sin(a);
}

// ---------------------------------------------------------------------------
// Split fp32 x -> fp16 hi/lo
// ---------------------------------------------------------------------------
__global__ void split_kernel(const float* __restrict__ in) {
    int i = blockIdx.x * blockDim.x + threadIdx.x;
    if (i >= MROWS * EE / 4) return;
    float4 v = ((const float4*)in)[i];
    uint32_t h0, l0, h1, l1;
    hsplit2(v.x, v.y, h0, l0);
    hsplit2(v.z, v.w, h1, l1);
    ((uint2*)g_xh)[i] = make_uint2(h0, h1);
    ((uint2*)g_xl)[i] = make_uint2(l0, l1);
}

// ---------------------------------------------------------------------------
// Transpose: in [R][C] fp32 -> out [C][R] fp16 (hi only)
// ---------------------------------------------------------------------------
__global__ void transpose_h_kernel(const float* __restrict__ in,
                                   int R, int C, int which) {
    __shared__ float t[32][33];
    __half* oh = which ? g_wph : g_wqh;
    int bx = blockIdx.x * 32, by = blockIdx.y * 32;
#pragma unroll
    for (int i = threadIdx.y; i < 32; i += 8)
        t[i][threadIdx.x] = in[(size_t)(by + i) * C + bx + threadIdx.x];
    __syncthreads();
#pragma unroll
    for (int i = threadIdx.y; i < 32; i += 8)
        oh[(size_t)(bx + i) * R + by + threadIdx.x] =
            __float2half(t[threadIdx.x][i]);
}

// ---------------------------------------------------------------------------
// HMMA GEMM, fp16 A-split: D = (Ah+Al) * Bh.  CTA 128x128, K-chunk 64,
// cp.async 2-stage pipeline (48KB/stage), 2 CTAs/SM.
// MODE 0: A=g_xh/xl, B=g_wqh; epi = bias + RoPE (+1/8 on Q), fp16 out to
//         Q(hi/lo) / K / V.
// MODE 1: A=g_ch/cl, B=g_wph; epi = bias -> Cout fp32.
// ---------------------------------------------------------------------------
#define OFF_AH 0
#define OFF_AL 16384
#define OFF_BH 32768
#define STAGE_BYTES 49152
#define GEMM_SMEM_BYTES (2*STAGE_BYTES + 1024)

template <int MODE>
__global__ __launch_bounds__(256, 2)
void gemm_mma(const float* __restrict__ bias, float* __restrict__ Cout) {
    extern __shared__ char smem_raw[];
    const uint32_t sb = smem_u32(smem_raw);
    const uint32_t tiles = (sb + 1023u) & ~1023u;

    const __half* Ah = (MODE == 0) ? g_xh : g_ch;
    const __half* Al = (MODE == 0) ? g_xl : g_cl;
    const __half* Bh = (MODE == 0) ? g_wqh : g_wph;

    const int tid = threadIdx.x;
    const int lane = tid & 31;
    const int warp = tid >> 5;
    const int wm = warp >> 1;
    const int wn = warp & 1;
    const int bm = blockIdx.y * 128;
    const int bn = blockIdx.x * 128;

    float acc[2][8][4];
#pragma unroll
    for (int mt = 0; mt < 2; mt++)
#pragma unroll
        for (int nt = 0; nt < 8; nt++)
#pragma unroll
            for (int c = 0; c < 4; c++) acc[mt][nt][c] = 0.f;

    // cp.async copy mapping: 1024 16B-lines per 16KB tile; thread handles
    // lines tid + p*256 (p=0..3): row = crow + p*32, seg fixed.
    const int crow = tid >> 3;
    const int cseg = tid & 7;
    const uint32_t s_sw =
        (uint32_t)((crow * 128 + cseg * 16) ^ ((crow & 7) << 4));
    const size_t gA0 = (size_t)(bm + crow) * 1024 + cseg * 8;
    const size_t gB0 = (size_t)(bn + crow) * 1024 + cseg * 8;

#define GEMM_ISSUE(c_, st_) do {                                           \
    uint32_t base_ = tiles + (st_) * STAGE_BYTES;                          \
    size_t gk_ = (size_t)(c_) * 64;                                        \
    _Pragma("unroll")                                                      \
    for (int p_ = 0; p_ < 4; p_++) {                                       \
        uint32_t sw_ = s_sw + p_ * 4096;                                   \
        size_t ga_ = gA0 + gk_ + (size_t)p_ * 32 * 1024;                   \
        size_t gb_ = gB0 + gk_ + (size_t)p_ * 32 * 1024;                   \
        CP_ASYNC16(base_ + OFF_AH + sw_, Ah + ga_);                        \
        CP_ASYNC16(base_ + OFF_AL + sw_, Al + ga_);                        \
        CP_ASYNC16(base_ + OFF_BH + sw_, Bh + gb_);                        \
    }                                                                      \
    CP_COMMIT();                                                           \
} while (0)

    // fragment addressing
    const int mat = lane >> 3;
    const int rr = lane & 7;
    const int a_row_base = wm * 32 + (mat & 1) * 8 + rr;
    const uint32_t a_k16 = (uint32_t)((mat >> 1) * 16);
    const int b_row_base = wn * 64 + (mat >> 1) * 8 + rr;
    const uint32_t b_k16 = (uint32_t)((mat & 1) * 16);

    uint32_t a_rel[2], a_xor[2], b_rel[4], b_xor[4];
#pragma unroll
    for (int mt = 0; mt < 2; mt++) {
        int row = a_row_base + mt * 16;
        a_rel[mt] = (uint32_t)(row * 128);
        a_xor[mt] = (uint32_t)((row & 7) << 4);
    }
#pragma unroll
    for (int p = 0; p < 4; p++) {
        int row = b_row_base + p * 16;
        b_rel[p] = (uint32_t)(row * 128);
        b_xor[p] = (uint32_t)((row & 7) << 4);
    }

    GEMM_ISSUE(0, 0);
    GEMM_ISSUE(1, 1);

#pragma unroll 1
    for (int c = 0; c < 16; c++) {
        const int st = c & 1;
        if (c + 1 < 16) { CP_WAIT1(); } else { CP_WAIT0(); }
        __syncthreads();
        const uint32_t stg = tiles + st * STAGE_BYTES;

#pragma unroll
        for (int ks = 0; ks < 4; ks++) {
            const uint32_t ksb = (uint32_t)(ks * 32);
            uint32_t ah[2][4], al[2][4], bf[4][4];
#pragma unroll
            for (int mt = 0; mt < 2; mt++) {
                uint32_t ka = a_rel[mt] + ((ksb + a_k16) ^ a_xor[mt]);
                LDSM_X4(ah[mt][0], ah[mt][1], ah[mt][2], ah[mt][3],
                        stg + OFF_AH + ka);
                LDSM_X4(al[mt][0], al[mt][1], al[mt][2], al[mt][3],
                        stg + OFF_AL + ka);
            }
#pragma unroll
            for (int p = 0; p < 4; p++) {
                uint32_t kb = b_rel[p] + ((ksb + b_k16) ^ b_xor[p]);
                LDSM_X4(bf[p][0], bf[p][1], bf[p][2], bf[p][3],
                        stg + OFF_BH + kb);
            }
#pragma unroll
            for (int mt = 0; mt < 2; mt++)
#pragma unroll
                for (int nt = 0; nt < 8; nt++) {
                    int p = nt >> 1, hf = (nt & 1) * 2;
                    MMA_F16(acc[mt][nt], ah[mt], bf[p][hf], bf[p][hf + 1]);
                    MMA_F16(acc[mt][nt], al[mt], bf[p][hf], bf[p][hf + 1]);
                }
        }
        __syncthreads();
        if (c + 2 < 16) GEMM_ISSUE(c + 2, st);
    }

    // ---- epilogue ----
    const int tg = lane & 3;
    const int g = lane >> 2;
    const int colbase = bn + wn * 64;

#pragma unroll
    for (int nt = 0; nt < 8; nt++) {
        float2 bb = *(const float2*)(bias + colbase + nt * 8 + tg * 2);
#pragma unroll
        for (int mt = 0; mt < 2; mt++) {
            acc[mt][nt][0] += bb.x;
            acc[mt][nt][1] += bb.y;
            acc[mt][nt][2] += bb.x;
            acc[mt][nt][3] += bb.y;
        }
    }

    if (MODE == 0) {
        const int sec = colbase >> 10;             // 0=q 1=k 2=v
        const int h = (colbase & 1023) >> 6;
        if (sec < 2) {
            // fused RoPE: pair (j, j+32) lives in (nt, nt+4), same lane
#pragma unroll
            for (int mt = 0; mt < 2; mt++) {
                int m0 = bm + wm * 32 + mt * 16 + g;
#pragma unroll
                for (int nt = 0; nt < 4; nt++)
#pragma unroll
                    for (int cc = 0; cc < 4; cc++) {
                        int j = nt * 8 + tg * 2 + (cc & 1);
                        int sp = (m0 + (cc >> 1) * 8) & 2047;
                        float cf = g_cos[(sp << 5) | j];
                        float sf = g_sin[(sp << 5) | j];
                        float a1 = acc[mt][nt][cc], a2 = acc[mt][nt + 4][cc];
                        acc[mt][nt][cc]     = a1 * cf - a2 * sf;
                        acc[mt][nt + 4][cc] = a2 * cf + a1 * sf;
                    }
            }
        }
        if (sec == 0) {     // fold 1/sqrt(D) into Q
#pragma unroll
            for (int mt = 0; mt < 2; mt++)
#pragma unroll
                for (int nt = 0; nt < 8; nt++)
#pragma unroll
                    for (int cc = 0; cc < 4; cc++) acc[mt][nt][cc] *= 0.125f;
        }
        __half* bufh = (sec == 0) ? g_Qh : (sec == 1) ? g_Kh : g_Vh;
#pragma unroll
        for (int mt = 0; mt < 2; mt++) {
            int m0 = bm + wm * 32 + mt * 16 + g;
#pragma unroll
            for (int rh = 0; rh < 2; rh++) {
                int row = m0 + rh * 8;
                int b = row >> 11, sp = row & 2047;
                size_t base = (((size_t)(b * HH + h)) * SS + sp) * DD;
#pragma unroll
                for (int nt = 0; nt < 8; nt++) {
                    int d = nt * 8 + tg * 2;
                    if (sec == 0) {
                        uint32_t hi, lo;
                        hsplit2(acc[mt][nt][rh * 2], acc[mt][nt][rh * 2 + 1],
                                hi, lo);
                        *(uint32_t*)(bufh + base + d) = hi;
                        *(uint32_t*)(g_Ql + base + d) = lo;
                    } else {
                        __half2 hv = __floats2half2_rn(acc[mt][nt][rh * 2],
                                                       acc[mt][nt][rh * 2 + 1]);
                        *(__half2*)(bufh + base + d) = hv;
                    }
                }
            }
        }
    } else {
#pragma unroll
        for (int mt = 0; mt < 2; mt++) {
            int m0 = bm + wm * 32 + mt * 16 + g;
#pragma unroll
            for (int rh = 0; rh < 2; rh++) {
                int row = m0 + rh * 8;
#pragma unroll
                for (int nt = 0; nt < 8; nt++) {
                    int col = colbase + nt * 8 + tg * 2;
                    float2 v = make_float2(acc[mt][nt][rh * 2],
                                           acc[mt][nt][rh * 2 + 1]);
                    *(float2*)(Cout + (size_t)row * EE + col) = v;
                }
            }
        }
    }
#undef GEMM_ISSUE
}

// ---------------------------------------------------------------------------
// Tensor-core flash attention (fp16 A-split, fp32 softmax), cp.async
// double-buffered K/V tiles. CTA: 128 q rows, 8 warps x 16 rows, 64-key tiles.
// Writes ctx fp16 hi/lo to g_ch/g_cl in [b*S+s][e] layout.
// ---------------------------------------------------------------------------
#define FQH 0
#define FQL 16384
#define FKV0 32768
#define FKV_STAGE 16384
#define FLASH_SMEM_BYTES (65536 + 1024)

__global__ __launch_bounds__(256, 1)
void flash_mma() {
    extern __shared__ char smem_raw[];
    const uint32_t sb = smem_u32(smem_raw);
    const uint32_t tiles = (sb + 1023u) & ~1023u;
    char* tp = smem_raw + (tiles - sb);

    const int tid = threadIdx.x;
    const int lane = tid & 31;
    const int warp = tid >> 5;
    const int bh = blockIdx.y;
    const int qb = blockIdx.x;
    const int q0 = qb * 128;
    const size_t qkv_base = (size_t)bh * SS * DD;
    const int ktiles = 2 * qb + 2;

#define FLASH_ISSUE(kt_, st_) do {                                         \
    uint32_t kb_ = tiles + FKV0 + (st_) * FKV_STAGE;                       \
    size_t g0_ = qkv_base + (size_t)(kt_) * 64 * 64;                       \
    _Pragma("unroll")                                                      \
    for (int i_ = 0; i_ < 2; i_++) {                                       \
        int line_ = tid + i_ * 256;                                        \
        int row_ = line_ >> 3, seg_ = line_ & 7;                           \
        uint32_t sw_ =                                                     \
            (uint32_t)((row_ * 128 + seg_ * 16) ^ ((row_ & 7) << 4));      \
        size_t ga_ = g0_ + (size_t)row_ * 64 + seg_ * 8;                   \
        CP_ASYNC16(kb_ + sw_, g_Kh + ga_);                                 \
        CP_ASYNC16(kb_ + 8192 + sw_, g_Vh + ga_);                          \
    }                                                                      \
    CP_COMMIT();                                                           \
} while (0)

    FLASH_ISSUE(0, 0);
    if (ktiles > 1) FLASH_ISSUE(1, 1);

    // ---- load Q tile (128 x 64) hi/lo into smem ----
#pragma unroll
    for (int i = 0; i < 4; i++) {
        int sidx = tid + i * 256;           // 0..1023
        int row = sidx >> 3, sg = sidx & 7;
        uint32_t sw = (uint32_t)((row * 128 + sg * 16) ^ ((row & 7) << 4));
        size_t go = qkv_base + (size_t)(q0 + row) * DD + sg * 8;
        *(uint4*)(tp + FQH + sw) = *(const uint4*)(g_Qh + go);
        *(uint4*)(tp + FQL + sw) = *(const uint4*)(g_Ql + go);
    }
    __syncthreads();

    const int mat = lane >> 3;
    const int rr = lane & 7;
    const int g = lane >> 2;
    const int tg = lane & 3;

    // ---- Q fragments (A operand), 4 k16 steps over d, hi+lo ----
    uint32_t aqh[4][4], aql[4][4];
    {
        int row = warp * 16 + (mat & 1) * 8 + rr;
        uint32_t roff = (uint32_t)(row * 128);
        uint32_t x = (uint32_t)((row & 7) << 4);
#pragma unroll
        for (int ks = 0; ks < 4; ks++) {
            uint32_t col = (uint32_t)(ks * 32 + (mat >> 1) * 16);
            LDSM_X4(aqh[ks][0], aqh[ks][1], aqh[ks][2], aqh[ks][3],
                    tiles + FQH + roff + (col ^ x));
            LDSM_X4(aql[ks][0], aql[ks][1], aql[ks][2], aql[ks][3],
                    tiles + FQL + roff + (col ^ x));
        }
    }

    float O[8][4];
#pragma unroll
    for (int nt = 0; nt < 8; nt++)
#pragma unroll
        for (int c = 0; c < 4; c++) O[nt][c] = 0.f;
    float mrow[2] = {-INFINITY, -INFINITY};
    float lrow[2] = {0.f, 0.f};

    // K fragment addressing (B operand, n = keys)
    const int k_rowb = (mat >> 1) * 8 + rr;
    const uint32_t k_k16 = (uint32_t)((mat & 1) * 16);
    // V^T fragment addressing (trans: rows = keys, cols = d)
    const int v_rowb = (mat & 1) * 8 + rr;
    const uint32_t v_d16 = (uint32_t)((mat >> 1) * 16);

    const int warp_row_min = q0 + warp * 16;

#pragma unroll 1
    for (int kt = 0; kt < ktiles; kt++) {
        const int k0 = kt * 64;
        const int st = kt & 1;
        if (kt + 1 < ktiles) { CP_WAIT1(); } else { CP_WAIT0(); }
        __syncthreads();
        const uint32_t stgK = tiles + FKV0 + st * FKV_STAGE;
        const uint32_t stgV = stgK + 8192;

        // ---- scores S = (Qh+Ql) K^T ----
        float s[8][4];
#pragma unroll
        for (int nt = 0; nt < 8; nt++)
#pragma unroll
            for (int c = 0; c < 4; c++) s[nt][c] = 0.f;

#pragma unroll
        for (int np = 0; np < 4; np++) {
            int row = np * 16 + k_rowb;
            uint32_t roff = (uint32_t)(row * 128);
            uint32_t x = (uint32_t)((row & 7) << 4);
#pragma unroll
            for (int ks = 0; ks < 4; ks++) {
                uint32_t col = (uint32_t)(ks * 32) + k_k16;
                uint32_t kh[4];
                LDSM_X4(kh[0], kh[1], kh[2], kh[3],
                        stgK + roff + (col ^ x));
                MMA_F16(s[2*np],   aqh[ks], kh[0], kh[1]);
                MMA_F16(s[2*np],   aql[ks], kh[0], kh[1]);
                MMA_F16(s[2*np+1], aqh[ks], kh[2], kh[3]);
                MMA_F16(s[2*np+1], aql[ks], kh[2], kh[3]);
            }
        }

        // ---- causal mask ----
        if (k0 + 63 > warp_row_min) {
#pragma unroll
            for (int nt = 0; nt < 8; nt++)
#pragma unroll
                for (int c = 0; c < 4; c++) {
                    int col = k0 + nt * 8 + tg * 2 + (c & 1);
                    int rw = warp_row_min + g + (c >> 1) * 8;
                    if (col > rw) s[nt][c] = -1e30f;
                }
        }

        // ---- online softmax ----
#pragma unroll
        for (int rh = 0; rh < 2; rh++) {
            float vm = -INFINITY;
#pragma unroll
            for (int nt = 0; nt < 8; nt++)
                vm = fmaxf(vm, fmaxf(s[nt][rh*2], s[nt][rh*2+1]));
            vm = fmaxf(vm, __shfl_xor_sync(0xffffffffu, vm, 1));
            vm = fmaxf(vm, __shfl_xor_sync(0xffffffffu, vm, 2));
            float mn = fmaxf(mrow[rh], vm);
            float sc = __expf(mrow[rh] - mn);
            mrow[rh] = mn;
            lrow[rh] *= sc;
            float psum = 0.f;
#pragma unroll
            for (int nt = 0; nt < 8; nt++) {
                float p0 = __expf(s[nt][rh*2]   - mn);
                float p1 = __expf(s[nt][rh*2+1] - mn);
                s[nt][rh*2] = p0;
                s[nt][rh*2+1] = p1;
                psum += p0 + p1;
                O[nt][rh*2]   *= sc;
                O[nt][rh*2+1] *= sc;
            }
            lrow[rh] += psum;
        }

        // ---- O += (Ph+Pl) V ----
#pragma unroll
        for (int ks = 0; ks < 4; ks++) {
            uint32_t ph[4], pl[4];
            hsplit2(s[2*ks][0],   s[2*ks][1],   ph[0], pl[0]);
            hsplit2(s[2*ks][2],   s[2*ks][3],   ph[1], pl[1]);
            hsplit2(s[2*ks+1][0], s[2*ks+1][1], ph[2], pl[2]);
            hsplit2(s[2*ks+1][2], s[2*ks+1][3], ph[3], pl[3]);

            int row = ks * 16 + v_rowb;
            uint32_t roff = (uint32_t)(row * 128);
            uint32_t x = (uint32_t)((row & 7) << 4);
#pragma unroll
            for (int dp = 0; dp < 4; dp++) {
                uint32_t col = (uint32_t)(dp * 32) + v_d16;
                uint32_t vh[4];
                LDSM_X4_T(vh[0], vh[1], vh[2], vh[3],
                          stgV + roff + (col ^ x));
                MMA_F16(O[2*dp],   ph, vh[0], vh[1]);
                MMA_F16(O[2*dp],   pl, vh[0], vh[1]);
                MMA_F16(O[2*dp+1], ph, vh[2], vh[3]);
                MMA_F16(O[2*dp+1], pl, vh[2], vh[3]);
            }
        }
        __syncthreads();
        if (kt + 2 < ktiles) FLASH_ISSUE(kt + 2, st);
    }

    // ---- epilogue: 1/l, split to fp16 hi/lo, write ctx ----
    float inv[2];
#pragma unroll
    for (int rh = 0; rh < 2; rh++) {
        float l = lrow[rh];
        l += __shfl_xor_sync(0xffffffffu, l, 1);
        l += __shfl_xor_sync(0xffffffffu, l, 2);
        inv[rh] = 1.f / l;
    }
    const int b = bh >> 4, h = bh & 15;
#pragma unroll
    for (int rh = 0; rh < 2; rh++) {
        int sp = q0 + warp * 16 + g + rh * 8;
        size_t base = ((size_t)(b * SS + sp)) * EE + h * DD;
#pragma unroll
        for (int nt = 0; nt < 8; nt++) {
            int d = nt * 8 + tg * 2;
            uint32_t hi, lo;
            hsplit2(O[nt][rh*2] * inv[rh], O[nt][rh*2+1] * inv[rh], hi, lo);
            *(uint32_t*)(g_ch + base + d) = hi;
            *(uint32_t*)(g_cl + base + d) = lo;
        }
    }
#undef FLASH_ISSUE
}

// ---------------------------------------------------------------------------
// Launch
// ---------------------------------------------------------------------------
extern "C" void kernel_launch(void* const* d_in, const int* in_sizes, int n_in,
                              void* d_out, int out_size) {
    const float* x      = (const float*)d_in[0];   // [4,2048,1024]
    const float* w_qkv  = (const float*)d_in[1];   // [1024,3072]
    const float* b_qkv  = (const float*)d_in[2];   // [3072]
    const float* w_proj = (const float*)d_in[3];   // [1024,1024]
    const float* b_proj = (const float*)d_in[4];   // [1024]
    float* out = (float*)d_out;                    // [4,2048,1024]

    cudaFuncSetAttribute(gemm_mma<0>, cudaFuncAttributeMaxDynamicSharedMemorySize,
                         GEMM_SMEM_BYTES);
    cudaFuncSetAttribute(gemm_mma<1>, cudaFuncAttributeMaxDynamicSharedMemorySize,
                         GEMM_SMEM_BYTES);
    cudaFuncSetAttribute(flash_mma, cudaFuncAttributeMaxDynamicSharedMemorySize,
                         FLASH_SMEM_BYTES);

    // 1) RoPE table
    rope_table_kernel<<<(SS * 32 + 255) / 256, 256>>>();

    // 2) Split x; transpose weights to fp16 [N][K]
    split_kernel<<<(MROWS * EE / 4 + 255) / 256, 256>>>(x);
    {
        dim3 blk(32, 8);
        transpose_h_kernel<<<dim3(3072 / 32, 1024 / 32), blk>>>(w_qkv, 1024, 3072, 0);
        transpose_h_kernel<<<dim3(1024 / 32, 1024 / 32), blk>>>(w_proj, 1024, 1024, 1);
    }

    // 3) QKV GEMM (HMMA) -> fp16 Q(hi/lo)/K/V with fused bias+RoPE+scale
    gemm_mma<0><<<dim3(24, 64), 256, GEMM_SMEM_BYTES>>>(b_qkv, nullptr);

    // 4) Tensor-core flash attention -> fp16 hi/lo ctx
    flash_mma<<<dim3(SS / 128, BB * HH), 256, FLASH_SMEM_BYTES>>>();

    // 5) Output projection (HMMA) -> d_out
    gemm_mma<1><<<dim3(8, 64), 256, GEMM_SMEM_BYTES>>>(b_proj, out);
}